// round 4
// baseline (speedup 1.0000x reference)
#include <cuda_runtime.h>
#include <cuda_bf16.h>

// PCEN: M_t = (1-s) M_{t-1} + s x_t  (per [b,f] row along T),
// out = (x / (EPS + M)^alpha + bias)^power - bias^power
//
// 8 rows per CTA, software-pipelined: prefetch row r+1 (registers) while
// computing row r, so DRAM traffic overlaps the MUFU-heavy epilogue.
// Per row: 256 threads x 8 contiguous elems, scaled linear-recurrence scan
// (m' = M/s so the recurrence is a single FMA per element).

#define T_LEN 2048
#define NTHREADS 256
#define PER_THREAD 8
#define NWARPS (NTHREADS / 32)
#define ROWS_PER_CTA 8
#define ROW_F4 (T_LEN / 4)   // 512 float4 per row

__device__ __forceinline__ float fast_lg2(float x) {
    float r;
    asm("lg2.approx.f32 %0, %1;" : "=f"(r) : "f"(x));
    return r;
}
__device__ __forceinline__ float fast_ex2(float x) {
    float r;
    asm("ex2.approx.f32 %0, %1;" : "=f"(r) : "f"(x));
    return r;
}

__global__ __launch_bounds__(NTHREADS)
void pcen_kernel(const float* __restrict__ x,
                 const float* __restrict__ alpha_p,
                 const float* __restrict__ power_p,
                 const float* __restrict__ bias_p,
                 float* __restrict__ out)
{
    const float s  = 0.015f;
    const float c1 = 0.985f;      // 1 - s
    const float EPSv = 1e-9f;

    const int tid  = threadIdx.x;
    const int lane = tid & 31;
    const int warp = tid >> 5;

    // Decay factor for one 8-element segment and its powers.
    const float c2 = c1 * c1;
    const float c4 = c2 * c2;
    const float f1 = c4 * c4;        // c1^8   (= A8)
    const float f2 = f1 * f1;        // A8^2
    const float f4 = f2 * f2;        // A8^4
    const float f8 = f4 * f4;        // A8^8
    const float f16 = f8 * f8;       // A8^16
    const float f32 = f16 * f16;     // A8^32  (per-warp decay)

    // A8^lane by exact binary exponentiation (no MUFU).
    float p = 1.f;
    if (lane & 1)  p *= f1;
    if (lane & 2)  p *= f2;
    if (lane & 4)  p *= f4;
    if (lane & 8)  p *= f8;
    if (lane & 16) p *= f16;

    // Scalars (broadcast loads).
    const float alpha = __ldg(alpha_p);
    const float power = __ldg(power_p);
    const float bias  = __ldg(bias_p);
    const float nalpha = -alpha;
    const float bp = fast_ex2(power * fast_lg2(bias));   // bias^power

    __shared__ float sW[NWARPS];   // inclusive warp totals
    __shared__ float sE[NWARPS];   // exclusive carry entering each warp

    const size_t base = (size_t)blockIdx.x * ROWS_PER_CTA * T_LEN;
    const float4* xin = (const float4*)(x + base);
    float4* oout = (float4*)(out + base);
    const int idx = tid * 2;       // float4 index within a row

    // Preload row 0.
    float4 xa = xin[idx];
    float4 xb = xin[idx + 1];

    #pragma unroll 1
    for (int r = 0; r < ROWS_PER_CTA; r++) {
        // Prefetch next row while this row computes.
        float4 na, nb;
        if (r + 1 < ROWS_PER_CTA) {
            na = xin[(r + 1) * ROW_F4 + idx];
            nb = xin[(r + 1) * ROW_F4 + idx + 1];
        }

        float xv[PER_THREAD] = {xa.x, xa.y, xa.z, xa.w, xb.x, xb.y, xb.z, xb.w};

        // Thread-local scaled recurrence from zero: m'_i = c1*m'_{i-1} + x_i
        float b = 0.f;
        #pragma unroll
        for (int i = 0; i < PER_THREAD; i++)
            b = fmaf(c1, b, xv[i]);

        // Inclusive Kogge-Stone scan within warp: v_t = v_{t-d} * A8^d + v_t
        float v = b;
        float u;
        u = __shfl_up_sync(0xffffffffu, v, 1);  if (lane >= 1)  v = fmaf(u, f1,  v);
        u = __shfl_up_sync(0xffffffffu, v, 2);  if (lane >= 2)  v = fmaf(u, f2,  v);
        u = __shfl_up_sync(0xffffffffu, v, 4);  if (lane >= 4)  v = fmaf(u, f4,  v);
        u = __shfl_up_sync(0xffffffffu, v, 8);  if (lane >= 8)  v = fmaf(u, f8,  v);
        u = __shfl_up_sync(0xffffffffu, v, 16); if (lane >= 16) v = fmaf(u, f16, v);

        if (lane == 31) sW[warp] = v;
        __syncthreads();
        if (tid == 0) {
            float c = 0.f;
            #pragma unroll
            for (int w = 0; w < NWARPS; w++) {
                sE[w] = c;
                c = fmaf(c, f32, sW[w]);
            }
        }
        __syncthreads();

        // Carry entering this thread's segment:
        //   m_in = warp_carry * A8^lane + inclusive_scan(lane-1)
        float prev = __shfl_up_sync(0xffffffffu, v, 1);
        if (lane == 0) prev = 0.f;
        float m = fmaf(sE[warp], p, prev);

        // Recompute exact scaled recurrence, apply PCEN pointwise.
        float o[PER_THREAD];
        #pragma unroll
        for (int i = 0; i < PER_THREAD; i++) {
            m = fmaf(c1, m, xv[i]);                       // m' recurrence
            float arg = fmaf(s, m, EPSv);                 // EPS + M
            float inv = fast_ex2(nalpha * fast_lg2(arg)); // (EPS+M)^(-alpha)
            float z = fmaf(xv[i], inv, bias);
            o[i] = fast_ex2(power * fast_lg2(z)) - bp;
        }

        oout[r * ROW_F4 + idx]     = make_float4(o[0], o[1], o[2], o[3]);
        oout[r * ROW_F4 + idx + 1] = make_float4(o[4], o[5], o[6], o[7]);

        xa = na; xb = nb;
    }
}

extern "C" void kernel_launch(void* const* d_in, const int* in_sizes, int n_in,
                              void* d_out, int out_size)
{
    const float* x     = (const float*)d_in[0];
    const float* alpha = (const float*)d_in[1];
    const float* power = (const float*)d_in[2];
    const float* bias  = (const float*)d_in[3];
    float* out = (float*)d_out;

    int rows = in_sizes[0] / T_LEN;            // B*F = 16384
    int grid = rows / ROWS_PER_CTA;            // 2048
    pcen_kernel<<<grid, NTHREADS>>>(x, alpha, power, bias, out);
}

// round 5
// speedup vs baseline: 1.0131x; 1.0131x over previous
#include <cuda_runtime.h>
#include <cuda_bf16.h>

// PCEN: M_t = (1-s) M_{t-1} + s x_t  (per [b,f] row along T),
// out = (x / (EPS + M)^alpha + bias)^power - bias^power
//
// R2 structure (best measured): one CTA per row, 256 thr x 8 elems,
// scaled linear-recurrence scan (m' = M/s => one FMA per element).
// This round: outer exp2 moved off the MUFU pipe onto FMA pipe
// (magic-round split + degree-5 Taylor), cutting MUFU 4 -> 3 per element.

#define T_LEN 2048
#define NTHREADS 256
#define PER_THREAD 8
#define NWARPS (NTHREADS / 32)

__device__ __forceinline__ float fast_lg2(float x) {
    float r;
    asm("lg2.approx.f32 %0, %1;" : "=f"(r) : "f"(x));
    return r;
}
__device__ __forceinline__ float fast_ex2(float x) {
    float r;
    asm("ex2.approx.f32 %0, %1;" : "=f"(r) : "f"(x));
    return r;
}

// exp2 on the FMA/ALU pipes: k = rint(y) via magic-number trick,
// f = y - k in [-0.5, 0.5], 2^f by degree-5 Taylor (max rel err ~2.4e-6),
// scale by 2^k via exponent-field add. Valid for |y| < ~100 (here |y| <= ~35).
__device__ __forceinline__ float poly_ex2(float y) {
    const float MAGIC = 12582912.0f;              // 1.5 * 2^23
    float j = y + MAGIC;                          // round-to-nearest in low bits
    int   k = __float_as_int(j) - 0x4B400000;     // integer k
    float fk = j - MAGIC;                         // (float)k
    float f = y - fk;                             // f in [-0.5, 0.5]
    // 2^f Taylor: 1 + ln2 f + (ln2)^2/2 f^2 + ...
    float p;
    p = fmaf(1.3333558146e-3f, f, 9.6181291076e-3f);
    p = fmaf(p, f, 5.5504108664e-2f);
    p = fmaf(p, f, 2.4022650696e-1f);
    p = fmaf(p, f, 6.9314718056e-1f);
    p = fmaf(p, f, 1.0f);
    return __int_as_float(__float_as_int(p) + (k << 23));
}

__global__ __launch_bounds__(NTHREADS)
void pcen_kernel(const float* __restrict__ x,
                 const float* __restrict__ alpha_p,
                 const float* __restrict__ power_p,
                 const float* __restrict__ bias_p,
                 float* __restrict__ out)
{
    const float s  = 0.015f;
    const float c1 = 0.985f;      // 1 - s
    const float EPSv = 1e-9f;

    const int tid  = threadIdx.x;
    const int lane = tid & 31;
    const int warp = tid >> 5;

    const size_t base = (size_t)blockIdx.x * T_LEN;
    const float4* xin = (const float4*)(x + base);

    // Coalesced load of 8 contiguous elements per thread.
    float4 xa = xin[tid * 2];
    float4 xb = xin[tid * 2 + 1];
    float xv[PER_THREAD] = {xa.x, xa.y, xa.z, xa.w, xb.x, xb.y, xb.z, xb.w};

    // Thread-local scaled recurrence from zero: m'_i = c1*m'_{i-1} + x_i
    float b = 0.f;
    #pragma unroll
    for (int i = 0; i < PER_THREAD; i++)
        b = fmaf(c1, b, xv[i]);

    // Decay factor for one 8-element segment and its powers.
    const float c2 = c1 * c1;
    const float c4 = c2 * c2;
    const float f1 = c4 * c4;        // c1^8   (= A8)
    const float f2 = f1 * f1;        // A8^2
    const float f4 = f2 * f2;        // A8^4
    const float f8 = f4 * f4;        // A8^8
    const float f16 = f8 * f8;       // A8^16
    const float f32 = f16 * f16;     // A8^32  (per-warp decay)

    // Inclusive Kogge-Stone scan within warp: v_t = v_{t-d} * A8^d + v_t
    float v = b;
    float u;
    u = __shfl_up_sync(0xffffffffu, v, 1);  if (lane >= 1)  v = fmaf(u, f1,  v);
    u = __shfl_up_sync(0xffffffffu, v, 2);  if (lane >= 2)  v = fmaf(u, f2,  v);
    u = __shfl_up_sync(0xffffffffu, v, 4);  if (lane >= 4)  v = fmaf(u, f4,  v);
    u = __shfl_up_sync(0xffffffffu, v, 8);  if (lane >= 8)  v = fmaf(u, f8,  v);
    u = __shfl_up_sync(0xffffffffu, v, 16); if (lane >= 16) v = fmaf(u, f16, v);

    __shared__ float sW[NWARPS];   // inclusive warp totals
    __shared__ float sE[NWARPS];   // exclusive carry entering each warp
    if (lane == 31) sW[warp] = v;
    __syncthreads();
    if (tid == 0) {
        float c = 0.f;
        #pragma unroll
        for (int w = 0; w < NWARPS; w++) {
            sE[w] = c;
            c = fmaf(c, f32, sW[w]);
        }
    }
    __syncthreads();

    // Carry entering this thread's segment:
    //   m_in = warp_carry * A8^lane + inclusive_scan(lane-1)
    float prev = __shfl_up_sync(0xffffffffu, v, 1);
    if (lane == 0) prev = 0.f;

    // A8^lane by exact binary exponentiation (no MUFU).
    float p = 1.f;
    if (lane & 1)  p *= f1;
    if (lane & 2)  p *= f2;
    if (lane & 4)  p *= f4;
    if (lane & 8)  p *= f8;
    if (lane & 16) p *= f16;

    float m = fmaf(sE[warp], p, prev);

    // Scalars (broadcast loads).
    const float alpha = __ldg(alpha_p);
    const float power = __ldg(power_p);
    const float bias  = __ldg(bias_p);
    const float nalpha = -alpha;
    const float bp = poly_ex2(power * fast_lg2(bias));   // bias^power

    // Recompute exact scaled recurrence, apply PCEN pointwise.
    // Per element: MUFU lg2, MUFU ex2 (inner pow), MUFU lg2 (outer), poly ex2.
    float o[PER_THREAD];
    #pragma unroll
    for (int i = 0; i < PER_THREAD; i++) {
        m = fmaf(c1, m, xv[i]);                       // m' recurrence
        float arg = fmaf(s, m, EPSv);                 // EPS + M
        float inv = fast_ex2(nalpha * fast_lg2(arg)); // (EPS+M)^(-alpha)
        float z = fmaf(xv[i], inv, bias);
        o[i] = poly_ex2(power * fast_lg2(z)) - bp;
    }

    float4* oout = (float4*)(out + base);
    oout[tid * 2]     = make_float4(o[0], o[1], o[2], o[3]);
    oout[tid * 2 + 1] = make_float4(o[4], o[5], o[6], o[7]);
}

extern "C" void kernel_launch(void* const* d_in, const int* in_sizes, int n_in,
                              void* d_out, int out_size)
{
    const float* x     = (const float*)d_in[0];
    const float* alpha = (const float*)d_in[1];
    const float* power = (const float*)d_in[2];
    const float* bias  = (const float*)d_in[3];
    float* out = (float*)d_out;

    int rows = in_sizes[0] / T_LEN;   // B*F = 16384
    pcen_kernel<<<rows, NTHREADS>>>(x, alpha, power, bias, out);
}

// round 6
// speedup vs baseline: 1.1023x; 1.0881x over previous
#include <cuda_runtime.h>
#include <cuda_bf16.h>

// PCEN: M_t = (1-s) M_{t-1} + s x_t  (per [b,f] row along T),
// out = (x / (EPS + M)^alpha + bias)^power - bias^power
//
// One CTA (128 thr) per row of T=2048; 16 elems/thread.
// Coalesced LDG -> padded SMEM tile -> per-thread contiguous regs,
// scaled linear-recurrence scan (m' = M/s), epilogue identical to the
// minimal-instruction R2 form, outputs staged back through the tile so
// STG is coalesced too.

#define T_LEN 2048
#define NTHREADS 128
#define PER_THREAD 16
#define NWARPS (NTHREADS / 32)
#define ROW_F4 (T_LEN / 4)                 // 512 float4 per row
#define PAD_SLOT(k) ((k) + ((k) >> 3))     // 1 pad float4 per 8
#define TILE_F4 (ROW_F4 + (ROW_F4 >> 3))   // 576

__device__ __forceinline__ float fast_lg2(float x) {
    float r;
    asm("lg2.approx.f32 %0, %1;" : "=f"(r) : "f"(x));
    return r;
}
__device__ __forceinline__ float fast_ex2(float x) {
    float r;
    asm("ex2.approx.f32 %0, %1;" : "=f"(r) : "f"(x));
    return r;
}

__global__ __launch_bounds__(NTHREADS, 10)
void pcen_kernel(const float* __restrict__ x,
                 const float* __restrict__ alpha_p,
                 const float* __restrict__ power_p,
                 const float* __restrict__ bias_p,
                 float* __restrict__ out)
{
    const float s  = 0.015f;
    const float c1 = 0.985f;      // 1 - s
    const float EPSv = 1e-9f;

    __shared__ float4 tile[TILE_F4];
    __shared__ float  sW[NWARPS];

    const int tid  = threadIdx.x;
    const int lane = tid & 31;
    const int warp = tid >> 5;

    const size_t base = (size_t)blockIdx.x * T_LEN;
    const float4* xin = (const float4*)(x + base);
    float4* oout = (float4*)(out + base);

    // Fully-coalesced loads (lanes consecutive), front-batched (MLP=4).
    float4 ld0 = xin[0 * NTHREADS + tid];
    float4 ld1 = xin[1 * NTHREADS + tid];
    float4 ld2 = xin[2 * NTHREADS + tid];
    float4 ld3 = xin[3 * NTHREADS + tid];
    tile[PAD_SLOT(0 * NTHREADS + tid)] = ld0;
    tile[PAD_SLOT(1 * NTHREADS + tid)] = ld1;
    tile[PAD_SLOT(2 * NTHREADS + tid)] = ld2;
    tile[PAD_SLOT(3 * NTHREADS + tid)] = ld3;
    __syncthreads();   // bar1: tile(x) ready

    // Per-thread contiguous chunk: elements [tid*16, tid*16+16).
    float xv[PER_THREAD];
    #pragma unroll
    for (int j = 0; j < 4; j++) {
        float4 t4 = tile[PAD_SLOT(tid * 4 + j)];
        xv[4 * j + 0] = t4.x; xv[4 * j + 1] = t4.y;
        xv[4 * j + 2] = t4.z; xv[4 * j + 3] = t4.w;
    }

    // Thread-local scaled recurrence from zero (m' = M/s):
    // two independent 8-chains for ILP, merged with one FMA.
    float b0 = 0.f, b1 = 0.f;
    #pragma unroll
    for (int i = 0; i < 8; i++)  b0 = fmaf(c1, b0, xv[i]);
    #pragma unroll
    for (int i = 8; i < 16; i++) b1 = fmaf(c1, b1, xv[i]);

    // Decay powers.
    const float c2  = c1 * c1;
    const float c4  = c2 * c2;
    const float c8  = c4 * c4;       // c1^8
    const float a1  = c8 * c8;       // c1^16  (per-thread segment decay A)
    const float a2  = a1 * a1;       // A^2
    const float a4  = a2 * a2;       // A^4
    const float a8  = a4 * a4;       // A^8
    const float a16 = a8 * a8;       // A^16
    const float a32 = a16 * a16;     // A^32 (per-warp decay)

    float B = fmaf(b0, c8, b1);      // thread total

    // Inclusive Kogge-Stone warp scan: v_t = v_{t-d} * A^d + v_t
    float v = B;
    float u;
    u = __shfl_up_sync(0xffffffffu, v, 1);  if (lane >= 1)  v = fmaf(u, a1,  v);
    u = __shfl_up_sync(0xffffffffu, v, 2);  if (lane >= 2)  v = fmaf(u, a2,  v);
    u = __shfl_up_sync(0xffffffffu, v, 4);  if (lane >= 4)  v = fmaf(u, a4,  v);
    u = __shfl_up_sync(0xffffffffu, v, 8);  if (lane >= 8)  v = fmaf(u, a8,  v);
    u = __shfl_up_sync(0xffffffffu, v, 16); if (lane >= 16) v = fmaf(u, a16, v);

    if (lane == 31) sW[warp] = v;
    __syncthreads();   // bar2: sW ready; tile(x) fully consumed

    // Cross-warp carry, computed redundantly per-thread (broadcast LDS):
    // carry_w = sum_{w'<w} sW[w'] * A32^(w-1-w')
    float carry = 0.f;
    #pragma unroll
    for (int w = 0; w < NWARPS - 1; w++)
        if (warp > w) carry = fmaf(carry, a32, sW[w]);

    float prev = __shfl_up_sync(0xffffffffu, v, 1);
    if (lane == 0) prev = 0.f;

    // A^lane by exact binary exponentiation.
    float p = 1.f;
    if (lane & 1)  p *= a1;
    if (lane & 2)  p *= a2;
    if (lane & 4)  p *= a4;
    if (lane & 8)  p *= a8;
    if (lane & 16) p *= a16;

    float m = fmaf(carry, p, prev);   // scaled state entering this segment

    // Scalars.
    const float alpha = __ldg(alpha_p);
    const float power = __ldg(power_p);
    const float bias  = __ldg(bias_p);
    const float nalpha = -alpha;
    const float bp = fast_ex2(power * fast_lg2(bias));   // bias^power

    // Epilogue (minimal form): per elem 2 FFMA + lg2/mul/ex2 + FFMA + lg2/mul/ex2 + FADD.
    #pragma unroll
    for (int j = 0; j < 4; j++) {
        float4 o4;
        float o[4];
        #pragma unroll
        for (int e = 0; e < 4; e++) {
            const int i = 4 * j + e;
            m = fmaf(c1, m, xv[i]);                       // m' recurrence
            float arg = fmaf(s, m, EPSv);                 // EPS + M
            float inv = fast_ex2(nalpha * fast_lg2(arg)); // (EPS+M)^(-alpha)
            float z = fmaf(xv[i], inv, bias);
            o[e] = fast_ex2(power * fast_lg2(z)) - bp;
        }
        o4.x = o[0]; o4.y = o[1]; o4.z = o[2]; o4.w = o[3];
        tile[PAD_SLOT(tid * 4 + j)] = o4;                 // stage for coalesced STG
    }
    __syncthreads();   // bar3: tile(o) ready

    oout[0 * NTHREADS + tid] = tile[PAD_SLOT(0 * NTHREADS + tid)];
    oout[1 * NTHREADS + tid] = tile[PAD_SLOT(1 * NTHREADS + tid)];
    oout[2 * NTHREADS + tid] = tile[PAD_SLOT(2 * NTHREADS + tid)];
    oout[3 * NTHREADS + tid] = tile[PAD_SLOT(3 * NTHREADS + tid)];
}

extern "C" void kernel_launch(void* const* d_in, const int* in_sizes, int n_in,
                              void* d_out, int out_size)
{
    const float* x     = (const float*)d_in[0];
    const float* alpha = (const float*)d_in[1];
    const float* power = (const float*)d_in[2];
    const float* bias  = (const float*)d_in[3];
    float* out = (float*)d_out;

    int rows = in_sizes[0] / T_LEN;   // B*F = 16384
    pcen_kernel<<<rows, NTHREADS>>>(x, alpha, power, bias, out);
}